// round 14
// baseline (speedup 1.0000x reference)
#include <cuda_runtime.h>
#include <math_constants.h>
#include <cstdint>

#define NN   768
#define IN   68
#define KNB  8
#define EO   32
#define FEAT 264
#define XW   132
#define EMB  32
#define MPAIR 294528
#define EPS  1e-5f

#define NBLK   296        // 2 per SM on 148 SMs — co-resident by construction
#define NTHR   256
#define TILES_PER_G 312   // 48 a-tiles(16 rows) x pruned 64-col b-tiles
#define NTILES (2*TILES_PER_G)

// ---------------- scratch (device globals, no allocation) ----------------
__device__ int   g_idx[2][NN][KNB];
__device__ float g_e1[2][NN][EO];
__device__ float g_x[2][NN][XW];
__device__ float g_accum[4][XW];
__device__ __align__(16) float g_A[2][NN][EMB];
__device__ __align__(16) float g_B[2][NN][EMB];
__device__ unsigned g_cnt[4];
__device__ unsigned g_gen[4];

__device__ __forceinline__ float lrelu(float x) { return fmaxf(x, 0.01f * x); }

// ---- packed f32x2 helpers ----
__device__ __forceinline__ unsigned long long pk2(float lo, float hi) {
    unsigned long long r;
    asm("mov.b64 %0, {%1,%2};" : "=l"(r) : "f"(lo), "f"(hi));
    return r;
}
__device__ __forceinline__ void upk2(float& lo, float& hi, unsigned long long p) {
    asm("mov.b64 {%0,%1}, %2;" : "=f"(lo), "=f"(hi) : "l"(p));
}
__device__ __forceinline__ unsigned long long fma2(unsigned long long a,
                                                   unsigned long long b,
                                                   unsigned long long c) {
    unsigned long long d;
    asm("fma.rn.f32x2 %0, %1, %2, %3;" : "=l"(d) : "l"(a), "l"(b), "l"(c));
    return d;
}
__device__ __forceinline__ unsigned long long mul2(unsigned long long a,
                                                   unsigned long long b) {
    unsigned long long d;
    asm("mul.rn.f32x2 %0, %1, %2;" : "=l"(d) : "l"(a), "l"(b));
    return d;
}
__device__ __forceinline__ unsigned long long lrelu2(unsigned long long x,
                                                     unsigned long long c1,
                                                     unsigned long long c2) {
    unsigned long long ax = x & 0x7FFFFFFF7FFFFFFFull;
    return fma2(x, c1, mul2(ax, c2));
}

// ---- software grid barrier (cross-launch safe: generation counter) ----
__device__ __forceinline__ void grid_bar(int id) {
    __syncthreads();
    if (threadIdx.x == 0) {
        __threadfence();
        unsigned gen = *((volatile unsigned*)&g_gen[id]);
        unsigned v = atomicAdd(&g_cnt[id], 1);
        if (v == gridDim.x - 1) {
            *((volatile unsigned*)&g_cnt[id]) = 0;
            __threadfence();
            atomicAdd(&g_gen[id], 1);
        } else {
            while (*((volatile unsigned*)&g_gen[id]) == gen) __nanosleep(64);
        }
        __threadfence();
    }
    __syncthreads();
}

__global__ void __launch_bounds__(NTHR, 2) fused_kernel(
        const float* __restrict__ feat0,  const float* __restrict__ feat1,
        const float* __restrict__ ec1_w1, const float* __restrict__ ec1_b1,
        const float* __restrict__ ec1_w2, const float* __restrict__ ec1_b2,
        const float* __restrict__ ec2_w1, const float* __restrict__ ec2_b1,
        const float* __restrict__ ec2_w2, const float* __restrict__ ec2_b2,
        const float* __restrict__ bn_g,   const float* __restrict__ bn_b,
        const float* __restrict__ lin1_w, const float* __restrict__ lin1_b,
        const float* __restrict__ w2,     const float* __restrict__ b2,
        const float* __restrict__ w3,     const float* __restrict__ b3,
        float* __restrict__ out) {
    // big phase union: A coords(12.3K)/gather(17.4K); B gather(8K); C sx(4.2K);
    // D sA(2112)+sBT(8704)+sW2(4096)=14912
    __shared__ __align__(16) unsigned char su[17408];
    __shared__ float s1a[8][EO];
    __shared__ int   sidx[8][KNB];
    __shared__ float pacc[4][XW];
    __shared__ float sscale[FEAT], sshift[FEAT];
    __shared__ float sbe[8][EMB];
    __shared__ unsigned long long sW3a[16], sW3b[16], sB2[16];
    __shared__ float b3s[2];

    int tid = threadIdx.x, wid = tid >> 5, lane = tid & 31;
    int bx = blockIdx.x;
    int gb = bx >= 148 ? 1 : 0;
    int bb = bx - gb * 148;
    int node = bb * 8 + wid;
    bool act = bb < 96;                 // 96 blocks x 8 warps = 768 nodes per graph
    const float* featg = gb ? feat1 : feat0;

    // ================= phase A: KNN + EdgeConv1 =================
    if (bx == 0)
        for (int t = tid; t < 4 * XW; t += NTHR) ((float*)g_accum)[t] = 0.f;

    if (act) {
        float4* sc = (float4*)su;
        for (int t = tid; t < NN; t += NTHR)
            sc[t] = *(const float4*)(featg + t * IN);
        __syncthreads();
        {
            float4 ci = sc[node];
            float dloc[NN / 32];
#pragma unroll
            for (int t = 0; t < NN / 32; t++) {
                float4 cj = sc[lane + t * 32];
                dloc[t] = fabsf(ci.x - cj.x) + fabsf(ci.y - cj.y) +
                          fabsf(ci.z - cj.z) + fabsf(ci.w - cj.w);
            }
            for (int r = 0; r < KNB; r++) {
                float best = CUDART_INF_F;
                int bt = 0;
#pragma unroll
                for (int t = 0; t < NN / 32; t++)
                    if (dloc[t] < best) { best = dloc[t]; bt = t; }
                int bj = lane + bt * 32;
                unsigned long long key =
                    (((unsigned long long)__float_as_uint(best)) << 32) | (unsigned)bj;
#pragma unroll
                for (int off = 16; off; off >>= 1) {
                    unsigned long long other = __shfl_xor_sync(0xffffffffu, key, off);
                    if (other < key) key = other;
                }
                int wj = (int)(key & 0xffffffffu);
                if (lane == (wj & 31)) dloc[wj >> 5] = CUDART_INF_F;
                if (lane == 0) {
                    sidx[wid][r] = wj;
                    g_idx[gb][node][r] = wj;
                }
            }
        }
        __syncthreads();   // coords dead

        float (*sh)[KNB][IN] = (float (*)[KNB][IN])su;
        for (int t = lane; t < KNB * IN; t += 32) {
            int k = t / IN, f = t - k * IN;
            sh[wid][k][f] = featg[sidx[wid][k] * IN + f];
        }
        __syncwarp();
        float p0 = ec1_b1[lane], p1 = 0.f;
        for (int f = 0; f < IN; f += 2) {
#pragma unroll
            for (int k = 0; k < KNB; k++) {
                p0 = fmaf(sh[wid][k][f],     ec1_w1[(f * KNB + k) * EO + lane],       p0);
                p1 = fmaf(sh[wid][k][f + 1], ec1_w1[((f + 1) * KNB + k) * EO + lane], p1);
            }
        }
        s1a[wid][lane] = lrelu(p0 + p1);
        __syncwarp();
        float h = ec1_b2[lane];
#pragma unroll
        for (int k = 0; k < EO; k++)
            h = fmaf(s1a[wid][k], ec1_w2[k * EO + lane], h);
        g_e1[gb][node][lane] = lrelu(h);
    }
    grid_bar(0);

    // ================= phase B: EdgeConv2 + x + bn partials =================
    if (act) {
        float (*sh2)[KNB][EO] = (float (*)[KNB][EO])su;
        for (int t = tid; t < 4 * XW; t += NTHR) ((float*)pacc)[t] = 0.f;
        for (int t = lane; t < KNB * EO; t += 32) {
            int k = t >> 5, f = t & 31;
            sh2[wid][k][f] = g_e1[gb][g_idx[gb][node][k]][f];
        }
        __syncthreads();

        float p0 = ec2_b1[lane], p1 = 0.f;
        for (int f = 0; f < EO; f += 2) {
#pragma unroll
            for (int k = 0; k < KNB; k++) {
                p0 = fmaf(sh2[wid][k][f],     ec2_w1[(f * KNB + k) * EO + lane],       p0);
                p1 = fmaf(sh2[wid][k][f + 1], ec2_w1[((f + 1) * KNB + k) * EO + lane], p1);
            }
        }
        s1a[wid][lane] = lrelu(p0 + p1);
        __syncwarp();
        float h = ec2_b2[lane];
#pragma unroll
        for (int k = 0; k < EO; k++)
            h = fmaf(s1a[wid][k], ec2_w2[k * EO + lane], h);

        float* xp = g_x[gb][node];
        for (int f = lane; f < IN; f += 32) xp[f] = featg[node * IN + f];
        xp[IN + lane]      = g_e1[gb][node][lane];
        xp[IN + EO + lane] = lrelu(h);
        __syncthreads();

        float wa = (float)(NN - 1 - node);
        float wb = (float)node;
        for (int f = lane; f < XW; f += 32) {
            float v = g_x[gb][node][f];
            atomicAdd(&pacc[0][f], wa * v);
            atomicAdd(&pacc[1][f], wb * v);
            atomicAdd(&pacc[2][f], wa * v * v);
            atomicAdd(&pacc[3][f], wb * v * v);
        }
        __syncthreads();
        for (int t = tid; t < 4 * XW; t += NTHR)
            atomicAdd(&((float*)g_accum)[t], ((float*)pacc)[t]);
    }
    grid_bar(1);

    // ================= phase C: BN finalize + A/B (lin1 split) =================
    if (act) {
        for (int f = tid; f < XW; f += NTHR) {
            float inv = 1.0f / (2.0f * (float)MPAIR);
            float s1 = __ldcg(&g_accum[0][f]), s2 = __ldcg(&g_accum[1][f]);
            float q1 = __ldcg(&g_accum[2][f]), q2 = __ldcg(&g_accum[3][f]);
            float mu1 = s1 * inv, var1 = fmaf(-mu1, mu1, q1 * inv);
            float mu2 = s2 * inv, var2 = fmaf(-mu2, mu2, q2 * inv);
            float sc1 = bn_g[f]      * rsqrtf(var1 + EPS);
            float sc2 = bn_g[XW + f] * rsqrtf(var2 + EPS);
            sscale[f]      = sc1;
            sscale[XW + f] = sc2;
            sshift[f]      = bn_b[f]      - mu1 * sc1;
            sshift[XW + f] = bn_b[XW + f] - mu2 * sc2;
        }
        float (*sx)[XW] = (float (*)[XW])su;
        for (int f = lane; f < XW; f += 32) sx[wid][f] = g_x[gb][node][f];
        __syncthreads();

        float p = 0.f;
        for (int ff = wid; ff < FEAT; ff += 8)
            p = fmaf(sshift[ff], lin1_w[ff * EMB + lane], p);
        sbe[wid][lane] = p;
        __syncthreads();

        float a = lin1_b[lane];
#pragma unroll
        for (int w = 0; w < 8; w++) a += sbe[w][lane];
        float bacc = 0.f;
        for (int f = 0; f < XW; f++) {
            float xv = sx[wid][f];
            a    = fmaf(xv * sscale[f],      lin1_w[f * EMB + lane],        a);
            bacc = fmaf(xv * sscale[XW + f], lin1_w[(XW + f) * EMB + lane], bacc);
        }
        g_A[gb][node][lane] = a;
        g_B[gb][node][lane] = bacc;
    }
    grid_bar(2);

    // ================= phase D: pair tiles (16i x 64j, 4 pairs/thread) =========
    {
        float* sAp  = (float*)su;                 // [16][33]
        float* sBTp = (float*)(su + 2112);        // [32][68]
        float* sW2p = (float*)(su + 2112 + 8704); // [32][32]
        for (int t = tid; t < 256; t += NTHR)
            ((float4*)sW2p)[t] = ((const float4*)w2)[t];
        if (tid < 16) {
            sB2[tid]  = ((const unsigned long long*)b2)[tid];
            sW3a[tid] = pk2(w3[4 * tid],     w3[4 * tid + 2]);
            sW3b[tid] = pk2(w3[4 * tid + 1], w3[4 * tid + 3]);
        }
        if (tid < 2) b3s[tid] = b3[tid];

        const unsigned long long c1 = pk2(0.505f, 0.505f);
        const unsigned long long c2 = pk2(0.495f, 0.495f);
        const ulonglong2* wv = (const ulonglong2*)sW2p;
        int ty = tid >> 4, tx = tid & 15;

        for (int tu = bx; tu < NTILES; tu += NBLK) {
            int gg = tu >= TILES_PER_G ? 1 : 0;
            int id = tu - gg * TILES_PER_G;
            int a = 0, bcol = 0;
            for (;;) {
                int bmin = (16 * a + 1) >> 6;
                int cnt = 12 - bmin;
                if (id < cnt) { bcol = bmin + id; break; }
                id -= cnt; a++;
            }
            int i0 = a * 16, j0 = bcol * 64;

            __syncthreads();   // previous tile's smem reads done
            if (tid < 128) {
                float4 v = ((const float4*)g_A[gg][i0])[tid];
                int r = tid >> 3, c = (tid & 7) * 4;
                sAp[r * 33 + c]     = v.x;
                sAp[r * 33 + c + 1] = v.y;
                sAp[r * 33 + c + 2] = v.z;
                sAp[r * 33 + c + 3] = v.w;
            }
            for (int q = tid; q < 512; q += NTHR) {
                float4 v = ((const float4*)g_B[gg][j0])[q];
                int r = q >> 3, c = (q & 7) * 4;
                sBTp[(c + 0) * 68 + r] = v.x;
                sBTp[(c + 1) * 68 + r] = v.y;
                sBTp[(c + 2) * 68 + r] = v.z;
                sBTp[(c + 3) * 68 + r] = v.w;
            }
            __syncthreads();

            int i = i0 + ty, jb = j0 + 4 * tx;
            unsigned long long oa[4] = {0, 0, 0, 0}, ob[4] = {0, 0, 0, 0};

#pragma unroll
            for (int s = 0; s < 2; s++) {
                unsigned long long acc[4][8];
#pragma unroll
                for (int p = 0; p < 4; p++)
#pragma unroll
                    for (int m = 0; m < 8; m++) acc[p][m] = sB2[8 * s + m];

#pragma unroll 8
                for (int k = 0; k < EMB; k++) {
                    float av = sAp[ty * 33 + k];
                    float4 bv = *(const float4*)&sBTp[k * 68 + 4 * tx];
                    float f0 = lrelu(av + bv.x), f1 = lrelu(av + bv.y);
                    float f2 = lrelu(av + bv.z), f3 = lrelu(av + bv.w);
                    unsigned long long h0 = pk2(f0, f0), h1 = pk2(f1, f1);
                    unsigned long long h2 = pk2(f2, f2), h3 = pk2(f3, f3);
#pragma unroll
                    for (int q2 = 0; q2 < 4; q2++) {
                        ulonglong2 w = wv[k * 8 + 4 * s + q2];
                        acc[0][2 * q2]     = fma2(h0, w.x, acc[0][2 * q2]);
                        acc[0][2 * q2 + 1] = fma2(h0, w.y, acc[0][2 * q2 + 1]);
                        acc[1][2 * q2]     = fma2(h1, w.x, acc[1][2 * q2]);
                        acc[1][2 * q2 + 1] = fma2(h1, w.y, acc[1][2 * q2 + 1]);
                        acc[2][2 * q2]     = fma2(h2, w.x, acc[2][2 * q2]);
                        acc[2][2 * q2 + 1] = fma2(h2, w.y, acc[2][2 * q2 + 1]);
                        acc[3][2 * q2]     = fma2(h3, w.x, acc[3][2 * q2]);
                        acc[3][2 * q2 + 1] = fma2(h3, w.y, acc[3][2 * q2 + 1]);
                    }
                }
#pragma unroll
                for (int m = 0; m < 8; m++) {
                    int mg = 8 * s + m;
                    unsigned long long wa = sW3a[mg], wb = sW3b[mg];
#pragma unroll
                    for (int p = 0; p < 4; p++) {
                        unsigned long long hh = lrelu2(acc[p][m], c1, c2);
                        oa[p] = fma2(hh, wa, oa[p]);
                        ob[p] = fma2(hh, wb, ob[p]);
                    }
                }
            }

            long long obase = (long long)gg * MPAIR;
            int base = i * (2 * NN - 1 - i) / 2 - i - 1;
#pragma unroll
            for (int p = 0; p < 4; p++) {
                int j = jb + p;
                if (j > i) {
                    float lo, hi;
                    upk2(lo, hi, oa[p]); float r0 = lo + hi + b3s[0];
                    upk2(lo, hi, ob[p]); float r1 = lo + hi + b3s[1];
                    ((float2*)out)[obase + base + j] = make_float2(r0, r1);
                }
            }
        }
    }
}

// ---------------- launch ----------------
extern "C" void kernel_launch(void* const* d_in, const int* in_sizes, int n_in,
                              void* d_out, int out_size) {
    const float* feat0  = (const float*)d_in[0];
    const float* feat1  = (const float*)d_in[1];
    const float* ec1_w1 = (const float*)d_in[2];
    const float* ec1_b1 = (const float*)d_in[3];
    const float* ec1_w2 = (const float*)d_in[4];
    const float* ec1_b2 = (const float*)d_in[5];
    const float* ec2_w1 = (const float*)d_in[6];
    const float* ec2_b1 = (const float*)d_in[7];
    const float* ec2_w2 = (const float*)d_in[8];
    const float* ec2_b2 = (const float*)d_in[9];
    const float* bn_g   = (const float*)d_in[10];
    const float* bn_b   = (const float*)d_in[11];
    const float* lin1_w = (const float*)d_in[12];
    const float* lin1_b = (const float*)d_in[13];
    const float* lin2_w = (const float*)d_in[14];
    const float* lin2_b = (const float*)d_in[15];
    const float* lin3_w = (const float*)d_in[16];
    const float* lin3_b = (const float*)d_in[17];
    float* out = (float*)d_out;

    fused_kernel<<<NBLK, NTHR>>>(feat0, feat1,
                                 ec1_w1, ec1_b1, ec1_w2, ec1_b2,
                                 ec2_w1, ec2_b1, ec2_w2, ec2_b2,
                                 bn_g, bn_b, lin1_w, lin1_b,
                                 lin2_w, lin2_b, lin3_w, lin3_b, out);
}